// round 5
// baseline (speedup 1.0000x reference)
#include <cuda_runtime.h>
#include <math.h>
#include <stdint.h>

#define Bc 16
#define Lc 128
#define Dc 8
#define Hc 128
#define NLc 2

// ---------------- scratch (static device globals; no allocation) ----------------
__device__ __align__(16) float g_ts[Bc*Lc];
__device__ __align__(16) float g_h[Bc*Lc*Hc];
__device__ __align__(16) float g_sa[Bc*Lc*Hc];
__device__ __align__(16) float g_da[Bc*Lc*Hc];
__device__ __align__(16) float g_sm[Bc*Lc*Hc];
__device__ __align__(16) float g_aggpre[Bc*Lc*Hc];
__device__ __align__(16) float g_Wca[NLc*Hc*Hc];
__device__ __align__(16) float g_Wcm[NLc*Hc*Hc];
__device__ __align__(16) float g_ba[NLc*Hc];
__device__ __align__(16) float g_bm[NLc*Hc];

// ---------------- packed f32x2 helpers ----------------
__device__ __forceinline__ void fma2(unsigned long long &acc, unsigned long long a, unsigned long long b){
    asm("fma.rn.f32x2 %0, %1, %2, %0;" : "+l"(acc) : "l"(a), "l"(b));
}
__device__ __forceinline__ void unpack2(unsigned long long v, float &lo, float &hi){
    asm("mov.b64 {%0,%1}, %2;" : "=f"(lo), "=f"(hi) : "l"(v));
}
__device__ __forceinline__ void cp16(void* dst_smem, const void* src){
    unsigned sdst = (unsigned)__cvta_generic_to_shared(dst_smem);
    asm volatile("cp.async.cg.shared.global [%0], [%1], 16;" :: "r"(sdst), "l"(src));
}
__device__ __forceinline__ uint32_t smem_u32(const void* p){
    uint32_t a;
    asm("{ .reg .u64 t; cvta.to.shared.u64 t, %1; cvt.u32.u64 %0, t; }" : "=r"(a) : "l"(p));
    return a;
}
__device__ __forceinline__ void lds_v2u64(unsigned long long &a, unsigned long long &b, uint32_t addr){
    asm volatile("ld.shared.v2.u64 {%0,%1}, [%2];" : "=l"(a), "=l"(b) : "r"(addr));
}
__device__ __forceinline__ void sts_dup(uint32_t addr, float v){
    asm volatile("st.shared.v2.f32 [%0], {%1,%1};" :: "r"(addr), "f"(v));
}

// ---------------- cumsum of ts ----------------
__global__ void k_ts(const float* __restrict__ hist){
    int b = threadIdx.x;
    if(b < Bc){
        float c = 0.f;
        for(int t = 0; t < Lc; t++){
            float v = hist[(b*Lc+t)*Dc + 5];
            c += fmaxf(v, 0.f);
            g_ts[b*Lc+t] = c;
        }
    }
}

// ---------------- folded weights: Wc = We2 @ Wa1_e / Wm1_e (plus bias rows) ----------------
__global__ void k_prepwb(const float* __restrict__ We2, const float* __restrict__ be2,
                         const float* __restrict__ Wa1, const float* __restrict__ Wm1,
                         const float* __restrict__ ba1, const float* __restrict__ bm1){
    int l = blockIdx.x / 129, kk = blockIdx.x % 129;
    int c = threadIdx.x;
    __shared__ float ws[Hc];
    if(kk < Hc) ws[c] = We2[l*Hc*Hc + kk*Hc + c];
    else        ws[c] = be2[l*Hc + c];
    __syncthreads();
    const float* wa = Wa1 + l*3*Hc*Hc + 2*Hc*Hc;
    const float* wm = Wm1 + l*2*Hc*Hc + Hc*Hc;
    float sa = 0.f, sm = 0.f;
    #pragma unroll 4
    for(int r = 0; r < Hc; r++){ float w = ws[r]; sa += w*wa[r*Hc + c]; sm += w*wm[r*Hc + c]; }
    if(kk < Hc){
        g_Wca[(l*Hc + kk)*Hc + c] = sa;
        g_Wcm[(l*Hc + kk)*Hc + c] = sm;
    } else {
        g_ba[l*Hc + c] = sa + ba1[l*Hc + c];
        g_bm[l*Hc + c] = sm + bm1[l*Hc + c];
    }
}

// ---------------- h0 (16 rows per block) + sa/da/sm for layer 0 ----------------
__global__ __launch_bounds__(256)
void k_h0s(const float* __restrict__ hist, const float* __restrict__ mask,
           const float* __restrict__ Wp, const float* __restrict__ bp,
           const float* __restrict__ Wa1, const float* __restrict__ Wm1){
    int row0 = blockIdx.x * 16;
    int tid = threadIdx.x;
    int c = tid & 127, ty = tid >> 7;
    __shared__ float xs[16*Dc], hs[16*Hc], vmsh[16];
    if(tid < 128) xs[tid] = hist[(size_t)row0*Dc + tid];
    if(tid < 16)  vmsh[tid] = mask[row0 + tid] > 0.f ? 1.f : 0.f;
    __syncthreads();
    float acc[8];
    #pragma unroll
    for(int p = 0; p < 8; p++) acc[p] = bp[c];
    #pragma unroll
    for(int d = 0; d < Dc; d++){
        float w = Wp[d*Hc + c];
        #pragma unroll
        for(int p = 0; p < 8; p++) acc[p] += xs[(ty*8+p)*Dc + d] * w;
    }
    #pragma unroll
    for(int p = 0; p < 8; p++){
        int r = ty*8 + p;
        float h = acc[p] * vmsh[r];
        hs[r*Hc + c] = h;
        g_h[(size_t)(row0+r)*Hc + c] = h;
    }
    __syncthreads();
    const float* was = Wa1;
    const float* wad = was + Hc*Hc;
    const float* wms = Wm1;
    float aa[8], dd[8], mm[8];
    #pragma unroll
    for(int p = 0; p < 8; p++){ aa[p]=0.f; dd[p]=0.f; mm[p]=0.f; }
    #pragma unroll 4
    for(int k = 0; k < Hc; k++){
        float w1 = was[k*Hc + c], w2 = wad[k*Hc + c], w3 = wms[k*Hc + c];
        #pragma unroll
        for(int p = 0; p < 8; p++){
            float h = hs[(ty*8+p)*Hc + k];
            aa[p] += h*w1; dd[p] += h*w2; mm[p] += h*w3;
        }
    }
    #pragma unroll
    for(int p = 0; p < 8; p++){
        size_t r = (size_t)(row0 + ty*8 + p)*Hc + c;
        g_sa[r] = aa[p]; g_da[r] = dd[p]; g_sm[r] = mm[p];
    }
}

// ---------------- main fused kernel ----------------
// dynamic SMEM (floats): Tdup [0, 8192) -- 32KB, u64 (v,v) pairs for 32 k x 128 j
//                        Wa   [8192, 24576)  -- 64KB [k][c]
//                        Wm   [24576, 40960) -- 64KB [k][c]
extern __shared__ float dsm[];

__global__ __launch_bounds__(512, 1)
void k_main5(int l, const float* __restrict__ hist, const float* __restrict__ mask,
             const float* __restrict__ We1, const float* __restrict__ be1,
             const float* __restrict__ wa2, const float* __restrict__ ba2){
    float* Wa = dsm + 8192;
    float* Wm = dsm + 24576;
    __shared__ float we1i[4*Hc], be1s[Hc], sab[Hc], smb[Hc], wa2s[Hc];
    __shared__ float att[Lc], wsoft[Lc], red[8];

    int bi = blockIdx.x;
    int b = bi >> 7, i = bi & 127;
    int tid = threadIdx.x;
    int j = tid & 127;

    // async copy of both folded W matrices (f32, row-major [k][c])
    const float* gwa = g_Wca + l*Hc*Hc;
    const float* gwm = g_Wcm + l*Hc*Hc;
    #pragma unroll
    for(int q = 0; q < 8; q++){
        cp16(Wa + q*2048 + tid*4, gwa + q*2048 + tid*4);
        cp16(Wm + q*2048 + tid*4, gwm + q*2048 + tid*4);
    }
    asm volatile("cp.async.commit_group;" ::: "memory");

    if(tid < 128){
        // interleaved We1 row: we1i[k*4+q] = We1[q][k]
        #pragma unroll
        for(int q = 0; q < 4; q++) we1i[tid*4 + q] = We1[l*4*Hc + q*Hc + tid];
        be1s[tid] = be1[l*Hc + tid];
        sab[tid]  = g_sa[(size_t)bi*Hc + tid] + g_ba[l*Hc + tid];
        smb[tid]  = g_sm[(size_t)bi*Hc + tid] + g_bm[l*Hc + tid];
        wa2s[tid] = wa2[l*Hc + tid];
    }

    // edge features for this thread's j
    const float* hb_ = hist + (size_t)b*Lc*Dc;
    float lat_i = hb_[i*Dc + 0], lon_i = hb_[i*Dc + 1], src_i = hb_[i*Dc + 6];
    float ts_i = g_ts[b*Lc + i];
    float latj = hb_[j*Dc + 0], lonj = hb_[j*Dc + 1], srcj = hb_[j*Dc + 6];
    float tsj = g_ts[b*Lc + j];
    float dl = lat_i - latj, dn = lon_i - lonj;
    float dist = sqrtf(dl*dl + dn*dn + 1e-8f);
    float dtv = fabsf(ts_i - tsj) * (1.f/300.f);
    float ssv = (src_i == srcj) ? 1.f : 0.f;
    float diag = (j == i) ? 1.f : 0.f;
    float vldj = (mask[b*Lc + j] > 0.f) ? 1.f : 0.f;
    float vi   = (mask[b*Lc + i] > 0.f) ? 1.f : 0.f;

    // GEMM thread mapping: group g (0=attention/Wa, 1=message/Wm)
    int g  = tid >> 8;
    int t  = tid & 255;
    int tx = t & 15, ty = t >> 4;
    int jt = ty*8;
    int ca = tx*4, cb = 64 + tx*4;
    const float* Wg = g ? Wm : Wa;

    uint32_t tdup = smem_u32(dsm);                      // u64 area base
    uint32_t tstore = tdup + (uint32_t)j*8u;            // + (k&31)*1024
    uint32_t tload0 = tdup + (uint32_t)jt*8u;           // + kk*1024
    uint32_t wbase = smem_u32(Wg) + (uint32_t)ca*4u;    // + k*512

    int kgrp = (tid >> 7) & 3;   // build k-subgroup within chunk

    unsigned long long acc[32];
    #pragma unroll
    for(int q = 0; q < 32; q++) acc[q] = 0ull;

    asm volatile("cp.async.wait_group 0;" ::: "memory");

    // 4 chunks of 32 k: build Tdup chunk, then GEMM it
    for(int ch = 0; ch < 4; ch++){
        __syncthreads();   // previous chunk fully consumed / smem ready
        {
            int kb = ch*32 + kgrp*8;
            #pragma unroll
            for(int e = 0; e < 8; e++){
                int k = kb + e;
                float4 w = *(const float4*)&we1i[k*4];
                float v = fmaxf(dist*w.x + dtv*w.y + ssv*w.z + diag*w.w + be1s[k], 0.f);
                sts_dup(tstore + (uint32_t)((k & 31)*1024), v);
            }
        }
        __syncthreads();   // chunk built (also covers W/we1i on ch==0)

        #pragma unroll 4
        for(int kk = 0; kk < 32; kk++){
            int k = ch*32 + kk;
            unsigned long long t0,t1,t2,t3,t4,t5,t6,t7;
            uint32_t ta = tload0 + (uint32_t)(kk*1024);
            lds_v2u64(t0, t1, ta);
            lds_v2u64(t2, t3, ta + 16);
            lds_v2u64(t4, t5, ta + 32);
            lds_v2u64(t6, t7, ta + 48);
            unsigned long long w0,w1,w2,w3;
            uint32_t wa_ = wbase + (uint32_t)(k*512);
            lds_v2u64(w0, w1, wa_);
            lds_v2u64(w2, w3, wa_ + 256);
            fma2(acc[0], t0,w0); fma2(acc[1], t0,w1); fma2(acc[2], t0,w2); fma2(acc[3], t0,w3);
            fma2(acc[4], t1,w0); fma2(acc[5], t1,w1); fma2(acc[6], t1,w2); fma2(acc[7], t1,w3);
            fma2(acc[8], t2,w0); fma2(acc[9], t2,w1); fma2(acc[10],t2,w2); fma2(acc[11],t2,w3);
            fma2(acc[12],t3,w0); fma2(acc[13],t3,w1); fma2(acc[14],t3,w2); fma2(acc[15],t3,w3);
            fma2(acc[16],t4,w0); fma2(acc[17],t4,w1); fma2(acc[18],t4,w2); fma2(acc[19],t4,w3);
            fma2(acc[20],t5,w0); fma2(acc[21],t5,w1); fma2(acc[22],t5,w2); fma2(acc[23],t5,w3);
            fma2(acc[24],t6,w0); fma2(acc[25],t6,w1); fma2(acc[26],t6,w2); fma2(acc[27],t6,w3);
            fma2(acc[28],t7,w0); fma2(acc[29],t7,w1); fma2(acc[30],t7,w2); fma2(acc[31],t7,w3);
        }
    }

    // ---------------- attention epilogue (group 0) ----------------
    if(g == 0){
        const float* dab = g_da + (size_t)b*Lc*Hc;
        #pragma unroll
        for(int jj = 0; jj < 8; jj++){
            int jr = jt + jj;
            float4 d0 = *(const float4*)&dab[(size_t)jr*Hc + ca];
            float4 d1 = *(const float4*)&dab[(size_t)jr*Hc + cb];
            float u0,u1,u2,u3,u4,u5,u6,u7;
            unpack2(acc[jj*4+0], u0, u1); unpack2(acc[jj*4+1], u2, u3);
            unpack2(acc[jj*4+2], u4, u5); unpack2(acc[jj*4+3], u6, u7);
            float s = 0.f;
            s += wa2s[ca+0]*tanhf(sab[ca+0] + d0.x + u0);
            s += wa2s[ca+1]*tanhf(sab[ca+1] + d0.y + u1);
            s += wa2s[ca+2]*tanhf(sab[ca+2] + d0.z + u2);
            s += wa2s[ca+3]*tanhf(sab[ca+3] + d0.w + u3);
            s += wa2s[cb+0]*tanhf(sab[cb+0] + d1.x + u4);
            s += wa2s[cb+1]*tanhf(sab[cb+1] + d1.y + u5);
            s += wa2s[cb+2]*tanhf(sab[cb+2] + d1.z + u6);
            s += wa2s[cb+3]*tanhf(sab[cb+3] + d1.w + u7);
            #pragma unroll
            for(int m = 8; m > 0; m >>= 1) s += __shfl_xor_sync(0xffffffffu, s, m);
            if(tx == 0) att[jr] = s;
        }
    }
    __syncthreads();

    // ---------------- softmax over j (first 128 threads) ----------------
    const float inv = 0.088388347648318440550f;   // 1/sqrt(128)
    float sc = -1e9f, e = 0.f;
    if(tid < 128){
        float a = (att[tid] + ba2[l]) * inv;
        bool ok = (vldj > 0.f) && (vi > 0.f);
        sc = ok ? a : -1e9f;
        float m = sc;
        #pragma unroll
        for(int s2 = 16; s2 > 0; s2 >>= 1) m = fmaxf(m, __shfl_xor_sync(0xffffffffu, m, s2));
        if((tid & 31) == 0) red[tid >> 5] = m;
    }
    __syncthreads();
    float bmax = fmaxf(fmaxf(red[0], red[1]), fmaxf(red[2], red[3]));
    if(tid < 128){
        e = expf(sc - bmax);
        float s2 = e;
        #pragma unroll
        for(int m = 16; m > 0; m >>= 1) s2 += __shfl_xor_sync(0xffffffffu, s2, m);
        if((tid & 31) == 0) red[4 + (tid >> 5)] = s2;
    }
    __syncthreads();
    if(tid < 128){
        float tot = red[4]+red[5]+red[6]+red[7];
        wsoft[tid] = e / tot;
    }
    __syncthreads();

    // ---------------- message epilogue (group 1): weighted relu aggregation ----------------
    float* su = dsm;   // 16 rows x 128 c partials (Tdup region is dead now)
    if(g == 1){
        float agA[4], agB[4];
        #pragma unroll
        for(int p = 0; p < 4; p++){ agA[p] = 0.f; agB[p] = 0.f; }
        #pragma unroll
        for(int jj = 0; jj < 8; jj++){
            float wj = wsoft[jt + jj];
            float u0,u1,u2,u3,u4,u5,u6,u7;
            unpack2(acc[jj*4+0], u0, u1); unpack2(acc[jj*4+1], u2, u3);
            unpack2(acc[jj*4+2], u4, u5); unpack2(acc[jj*4+3], u6, u7);
            agA[0] += wj * fmaxf(smb[ca+0] + u0, 0.f);
            agA[1] += wj * fmaxf(smb[ca+1] + u1, 0.f);
            agA[2] += wj * fmaxf(smb[ca+2] + u2, 0.f);
            agA[3] += wj * fmaxf(smb[ca+3] + u3, 0.f);
            agB[0] += wj * fmaxf(smb[cb+0] + u4, 0.f);
            agB[1] += wj * fmaxf(smb[cb+1] + u5, 0.f);
            agB[2] += wj * fmaxf(smb[cb+2] + u6, 0.f);
            agB[3] += wj * fmaxf(smb[cb+3] + u7, 0.f);
        }
        #pragma unroll
        for(int p = 0; p < 4; p++){
            su[ty*Hc + ca + p] = agA[p];
            su[ty*Hc + cb + p] = agB[p];
        }
    }
    __syncthreads();
    if(tid < 128){
        float s = 0.f;
        #pragma unroll 4
        for(int t2 = 0; t2 < 16; t2++) s += su[t2*Hc + tid];
        g_aggpre[(size_t)bi*Hc + tid] = s;
    }
}

// ---------------- epilogue per 16 rows ----------------
__global__ __launch_bounds__(256)
void k_post2(int l, int has_next, const float* __restrict__ mask,
             const float* __restrict__ Wm2, const float* __restrict__ bm2,
             const float* __restrict__ Wo1, const float* __restrict__ bo1,
             const float* __restrict__ Wo2, const float* __restrict__ bo2,
             const float* __restrict__ lng, const float* __restrict__ lnb,
             const float* __restrict__ Wa1, const float* __restrict__ Wm1){
    int row0 = blockIdx.x * 16;
    int tid = threadIdx.x;
    int c = tid & 127, ty = tid >> 7;
    __shared__ float hs[16*Hc], as_[16*Hc], ag[16*Hc], op1[16*Hc];
    __shared__ float mu[16], rsd[16], vmsh[16];

    #pragma unroll
    for(int q = 0; q < 8; q++){
        int idx = q*256 + tid;
        hs[idx]  = g_h[(size_t)row0*Hc + idx];
        as_[idx] = g_aggpre[(size_t)row0*Hc + idx];
    }
    if(tid < 16) vmsh[tid] = mask[row0 + tid] > 0.f ? 1.f : 0.f;
    __syncthreads();

    float acc[8];
    const float* wm2 = Wm2 + l*Hc*Hc;
    #pragma unroll
    for(int p = 0; p < 8; p++) acc[p] = bm2[l*Hc + c];
    #pragma unroll 4
    for(int k = 0; k < Hc; k++){
        float w = wm2[k*Hc + c];
        #pragma unroll
        for(int p = 0; p < 8; p++) acc[p] += as_[(ty*8+p)*Hc + k] * w;
    }
    #pragma unroll
    for(int p = 0; p < 8; p++) ag[(ty*8+p)*Hc + c] = acc[p];
    __syncthreads();

    const float* wo1h = Wo1 + l*2*Hc*Hc;
    const float* wo1a = wo1h + Hc*Hc;
    #pragma unroll
    for(int p = 0; p < 8; p++) acc[p] = bo1[l*Hc + c];
    #pragma unroll 4
    for(int k = 0; k < Hc; k++){
        float w1 = wo1h[k*Hc + c], w2 = wo1a[k*Hc + c];
        #pragma unroll
        for(int p = 0; p < 8; p++)
            acc[p] += hs[(ty*8+p)*Hc + k]*w1 + ag[(ty*8+p)*Hc + k]*w2;
    }
    #pragma unroll
    for(int p = 0; p < 8; p++) op1[(ty*8+p)*Hc + c] = fmaxf(acc[p], 0.f);
    __syncthreads();

    const float* wo2 = Wo2 + l*Hc*Hc;
    #pragma unroll
    for(int p = 0; p < 8; p++) acc[p] = bo2[l*Hc + c];
    #pragma unroll 4
    for(int k = 0; k < Hc; k++){
        float w = wo2[k*Hc + c];
        #pragma unroll
        for(int p = 0; p < 8; p++) acc[p] += op1[(ty*8+p)*Hc + k] * w;
    }
    #pragma unroll
    for(int p = 0; p < 8; p++){
        int r = ty*8 + p;
        ag[r*Hc + c] = hs[r*Hc + c] + acc[p];
    }
    __syncthreads();

    {
        int row = tid >> 4, l16 = tid & 15;
        float s = 0.f, s2 = 0.f;
        #pragma unroll
        for(int q = 0; q < 8; q++){
            float v = ag[row*Hc + l16 + q*16];
            s += v; s2 += v*v;
        }
        #pragma unroll
        for(int m = 8; m > 0; m >>= 1){
            s  += __shfl_xor_sync(0xffffffffu, s, m);
            s2 += __shfl_xor_sync(0xffffffffu, s2, m);
        }
        if(l16 == 0){
            float m_ = s * (1.f/128.f);
            mu[row] = m_;
            rsd[row] = rsqrtf(s2 * (1.f/128.f) - m_*m_ + 1e-5f);
        }
    }
    __syncthreads();
    const float* lg = lng + l*Hc;
    const float* lb = lnb + l*Hc;
    #pragma unroll
    for(int p = 0; p < 8; p++){
        int r = ty*8 + p;
        float x = ag[r*Hc + c];
        float hn = ((x - mu[r]) * rsd[r] * lg[c] + lb[c]) * vmsh[r];
        g_h[(size_t)(row0+r)*Hc + c] = hn;
        hs[r*Hc + c] = hn;
    }

    if(has_next){
        __syncthreads();
        int ln = l + 1;
        const float* was = Wa1 + ln*3*Hc*Hc;
        const float* wad = was + Hc*Hc;
        const float* wms = Wm1 + ln*2*Hc*Hc;
        float aa[8], dd[8], mm[8];
        #pragma unroll
        for(int p = 0; p < 8; p++){ aa[p]=0.f; dd[p]=0.f; mm[p]=0.f; }
        #pragma unroll 4
        for(int k = 0; k < Hc; k++){
            float w1 = was[k*Hc + c], w2 = wad[k*Hc + c], w3 = wms[k*Hc + c];
            #pragma unroll
            for(int p = 0; p < 8; p++){
                float h = hs[(ty*8+p)*Hc + k];
                aa[p] += h*w1; dd[p] += h*w2; mm[p] += h*w3;
            }
        }
        #pragma unroll
        for(int p = 0; p < 8; p++){
            size_t r = (size_t)(row0 + ty*8 + p)*Hc + c;
            g_sa[r] = aa[p]; g_da[r] = dd[p]; g_sm[r] = mm[p];
        }
    }
}

// ---------------- decoder ----------------
__global__ void k_dec(const float* __restrict__ hist, const float* __restrict__ mask,
                      const float* __restrict__ hg, const float* __restrict__ hb,
                      const float* __restrict__ Wh1, const float* __restrict__ bh1,
                      const float* __restrict__ Wh2, const float* __restrict__ bh2,
                      float* __restrict__ out){
    int b = blockIdx.x; int t = threadIdx.x;
    __shared__ float x[136], xn[136], hid[Hc];
    __shared__ float red2[4];
    float mv = mask[b*Lc + t];
    float s = mv;
    #pragma unroll
    for(int sft = 16; sft > 0; sft >>= 1) s += __shfl_xor_sync(0xffffffffu, s, sft);
    if((t & 31) == 0) red2[t >> 5] = s;
    __syncthreads();
    float tot = red2[0]+red2[1]+red2[2]+red2[3];
    int vc = (int)tot;
    vc = min(max(vc, 1), Lc);
    int last = vc - 1;

    if(t < Dc) x[t] = hist[((size_t)b*Lc + last)*Dc + t];
    x[Dc + t] = g_h[((size_t)b*Lc + last)*Hc + t];
    __syncthreads();
    float s1 = x[t] + ((t < 8) ? x[128 + t] : 0.f);
    #pragma unroll
    for(int sft = 16; sft > 0; sft >>= 1) s1 += __shfl_xor_sync(0xffffffffu, s1, sft);
    __syncthreads();
    if((t & 31) == 0) red2[t >> 5] = s1;
    __syncthreads();
    float mu = (red2[0]+red2[1]+red2[2]+red2[3]) * (1.f/136.f);
    float d0 = x[t] - mu;
    float s2 = d0*d0;
    if(t < 8){ float d1 = x[128 + t] - mu; s2 += d1*d1; }
    #pragma unroll
    for(int sft = 16; sft > 0; sft >>= 1) s2 += __shfl_xor_sync(0xffffffffu, s2, sft);
    __syncthreads();
    if((t & 31) == 0) red2[t >> 5] = s2;
    __syncthreads();
    float rs = rsqrtf((red2[0]+red2[1]+red2[2]+red2[3]) * (1.f/136.f) + 1e-5f);
    xn[t] = (x[t] - mu) * rs * hg[t] + hb[t];
    if(t < 8) xn[128 + t] = (x[128 + t] - mu) * rs * hg[128 + t] + hb[128 + t];
    __syncthreads();
    float h_ = bh1[t];
    for(int k = 0; k < 136; k++) h_ += xn[k]*Wh1[k*Hc + t];
    hid[t] = fmaxf(h_, 0.f);
    __syncthreads();
    if(t < 24){
        float p = bh2[t];
        for(int k = 0; k < Hc; k++) p += hid[k]*Wh2[k*24 + t];
        if(isnan(p)) p = 0.f;
        else if(isinf(p)) p = (p > 0.f) ? 1e4f : -1e4f;
        out[b*24 + t] = p;
    }
}

__global__ void k_copyh(float* __restrict__ out){
    int i = blockIdx.x*blockDim.x + threadIdx.x;
    out[384 + i] = g_h[i];
}

// ---------------- launch ----------------
extern "C" void kernel_launch(void* const* d_in, const int* in_sizes, int n_in,
                              void* d_out, int out_size){
    const float* hist = (const float*)d_in[0];
    const float* mask = (const float*)d_in[1];
    const float* Wp   = (const float*)d_in[2];
    const float* bp   = (const float*)d_in[3];
    const float* We1  = (const float*)d_in[4];
    const float* be1  = (const float*)d_in[5];
    const float* We2  = (const float*)d_in[6];
    const float* be2  = (const float*)d_in[7];
    const float* Wa1  = (const float*)d_in[8];
    const float* ba1  = (const float*)d_in[9];
    const float* wa2  = (const float*)d_in[10];
    const float* ba2  = (const float*)d_in[11];
    const float* Wm1  = (const float*)d_in[12];
    const float* bm1  = (const float*)d_in[13];
    const float* Wm2  = (const float*)d_in[14];
    const float* bm2  = (const float*)d_in[15];
    const float* Wo1  = (const float*)d_in[16];
    const float* bo1  = (const float*)d_in[17];
    const float* Wo2  = (const float*)d_in[18];
    const float* bo2  = (const float*)d_in[19];
    const float* lng  = (const float*)d_in[20];
    const float* lnb  = (const float*)d_in[21];
    const float* hg   = (const float*)d_in[22];
    const float* hbv  = (const float*)d_in[23];
    const float* Wh1  = (const float*)d_in[24];
    const float* bh1  = (const float*)d_in[25];
    const float* Wh2  = (const float*)d_in[26];
    const float* bh2  = (const float*)d_in[27];
    float* out = (float*)d_out;

    cudaFuncSetAttribute(k_main5, cudaFuncAttributeMaxDynamicSharedMemorySize, 163840);

    k_ts<<<1, 32>>>(hist);
    k_prepwb<<<NLc*129, Hc>>>(We2, be2, Wa1, Wm1, ba1, bm1);
    k_h0s<<<Bc*Lc/16, 256>>>(hist, mask, Wp, bp, Wa1, Wm1);
    for(int l = 0; l < NLc; l++){
        k_main5<<<Bc*Lc, 512, 163840>>>(l, hist, mask, We1, be1, wa2, ba2);
        k_post2<<<Bc*Lc/16, 256>>>(l, (l+1 < NLc) ? 1 : 0, mask,
                                   Wm2, bm2, Wo1, bo1, Wo2, bo2, lng, lnb, Wa1, Wm1);
    }
    k_dec<<<Bc, Hc>>>(hist, mask, hg, hbv, Wh1, bh1, Wh2, bh2, out);
    if(out_size >= 384 + Bc*Lc*Hc){
        k_copyh<<<(Bc*Lc*Hc)/256, 256>>>(out);
    }
}

// round 6
// speedup vs baseline: 1.0874x; 1.0874x over previous
#include <cuda_runtime.h>
#include <math.h>

#define Bc 16
#define Lc 128
#define Dc 8
#define Hc 128
#define NLc 2

// ---------------- scratch (static device globals; no allocation) ----------------
__device__ __align__(16) float g_ts[Bc*Lc];
__device__ __align__(16) float g_h[Bc*Lc*Hc];
__device__ __align__(16) float g_sa[Bc*Lc*Hc];
__device__ __align__(16) float g_da[Bc*Lc*Hc];
__device__ __align__(16) float g_sm[Bc*Lc*Hc];
__device__ __align__(16) float g_aggpre[Bc*Lc*Hc];
__device__ __align__(16) float g_Wca[NLc*Hc*Hc];
__device__ __align__(16) float g_Wcm[NLc*Hc*Hc];
__device__ __align__(16) float g_ba[NLc*Hc];
__device__ __align__(16) float g_bm[NLc*Hc];

// ---------------- packed f32x2 helpers ----------------
__device__ __forceinline__ void fma2(unsigned long long &acc, unsigned long long a, unsigned long long b){
    asm("fma.rn.f32x2 %0, %1, %2, %0;" : "+l"(acc) : "l"(a), "l"(b));
}
__device__ __forceinline__ unsigned long long pack2(float lo, float hi){
    unsigned long long r; asm("mov.b64 %0, {%1,%2};" : "=l"(r) : "f"(lo), "f"(hi)); return r;
}
__device__ __forceinline__ void unpack2(unsigned long long v, float &lo, float &hi){
    asm("mov.b64 {%0,%1}, %2;" : "=f"(lo), "=f"(hi) : "l"(v));
}
__device__ __forceinline__ void cp16(void* dst_smem, const void* src){
    unsigned sdst = (unsigned)__cvta_generic_to_shared(dst_smem);
    asm volatile("cp.async.cg.shared.global [%0], [%1], 16;" :: "r"(sdst), "l"(src));
}
// HW tanh approximation (MUFU.TANH, sm_75+): max abs err ~5e-4, plenty for 1e-3 gate.
__device__ __forceinline__ float tanh_fast(float x){
    float r; asm("tanh.approx.f32 %0, %1;" : "=f"(r) : "f"(x)); return r;
}

// ---------------- cumsum of ts ----------------
__global__ void k_ts(const float* __restrict__ hist){
    int b = threadIdx.x;
    if(b < Bc){
        float c = 0.f;
        for(int t = 0; t < Lc; t++){
            float v = hist[(b*Lc+t)*Dc + 5];
            c += fmaxf(v, 0.f);
            g_ts[b*Lc+t] = c;
        }
    }
}

// ---------------- folded weights: Wc = We2 @ Wa1_e / Wm1_e (plus bias rows) ----------------
__global__ void k_prepwb(const float* __restrict__ We2, const float* __restrict__ be2,
                         const float* __restrict__ Wa1, const float* __restrict__ Wm1,
                         const float* __restrict__ ba1, const float* __restrict__ bm1){
    int l = blockIdx.x / 129, kk = blockIdx.x % 129;
    int c = threadIdx.x;
    __shared__ float ws[Hc];
    if(kk < Hc) ws[c] = We2[l*Hc*Hc + kk*Hc + c];
    else        ws[c] = be2[l*Hc + c];
    __syncthreads();
    const float* wa = Wa1 + l*3*Hc*Hc + 2*Hc*Hc;
    const float* wm = Wm1 + l*2*Hc*Hc + Hc*Hc;
    float sa = 0.f, sm = 0.f;
    #pragma unroll 4
    for(int r = 0; r < Hc; r++){ float w = ws[r]; sa += w*wa[r*Hc + c]; sm += w*wm[r*Hc + c]; }
    if(kk < Hc){
        g_Wca[(l*Hc + kk)*Hc + c] = sa;
        g_Wcm[(l*Hc + kk)*Hc + c] = sm;
    } else {
        g_ba[l*Hc + c] = sa + ba1[l*Hc + c];
        g_bm[l*Hc + c] = sm + bm1[l*Hc + c];
    }
}

// ---------------- h0 (16 rows per block) + sa/da/sm for layer 0 ----------------
__global__ __launch_bounds__(256)
void k_h0s(const float* __restrict__ hist, const float* __restrict__ mask,
           const float* __restrict__ Wp, const float* __restrict__ bp,
           const float* __restrict__ Wa1, const float* __restrict__ Wm1){
    int row0 = blockIdx.x * 16;
    int tid = threadIdx.x;
    int c = tid & 127, ty = tid >> 7;
    __shared__ float xs[16*Dc], hs[16*Hc], vmsh[16];
    if(tid < 128) xs[tid] = hist[(size_t)row0*Dc + tid];
    if(tid < 16)  vmsh[tid] = mask[row0 + tid] > 0.f ? 1.f : 0.f;
    __syncthreads();
    float acc[8];
    #pragma unroll
    for(int p = 0; p < 8; p++) acc[p] = bp[c];
    #pragma unroll
    for(int d = 0; d < Dc; d++){
        float w = Wp[d*Hc + c];
        #pragma unroll
        for(int p = 0; p < 8; p++) acc[p] += xs[(ty*8+p)*Dc + d] * w;
    }
    #pragma unroll
    for(int p = 0; p < 8; p++){
        int r = ty*8 + p;
        float h = acc[p] * vmsh[r];
        hs[r*Hc + c] = h;
        g_h[(size_t)(row0+r)*Hc + c] = h;
    }
    __syncthreads();
    const float* was = Wa1;
    const float* wad = was + Hc*Hc;
    const float* wms = Wm1;
    float aa[8], dd[8], mm[8];
    #pragma unroll
    for(int p = 0; p < 8; p++){ aa[p]=0.f; dd[p]=0.f; mm[p]=0.f; }
    #pragma unroll 4
    for(int k = 0; k < Hc; k++){
        float w1 = was[k*Hc + c], w2 = wad[k*Hc + c], w3 = wms[k*Hc + c];
        #pragma unroll
        for(int p = 0; p < 8; p++){
            float h = hs[(ty*8+p)*Hc + k];
            aa[p] += h*w1; dd[p] += h*w2; mm[p] += h*w3;
        }
    }
    #pragma unroll
    for(int p = 0; p < 8; p++){
        size_t r = (size_t)(row0 + ty*8 + p)*Hc + c;
        g_sa[r] = aa[p]; g_da[r] = dd[p]; g_sm[r] = mm[p];
    }
}

// ---------------- main fused kernel: warp-specialized 8jx8c register-blocked GEMMs ----------------
extern __shared__ float dsm[];   // Ts 64KB | Wa 64KB | Wm 64KB

__global__ __launch_bounds__(512, 1)
void k_main3(int l, const float* __restrict__ hist, const float* __restrict__ mask,
             const float* __restrict__ We1, const float* __restrict__ be1,
             const float* __restrict__ wa2, const float* __restrict__ ba2){
    float* Ts = dsm;                 // [k][j]
    float* Wa = dsm + 16384;         // [k][c]
    float* Wm = dsm + 32768;         // [k][c]
    __shared__ float we1s[4*Hc], be1s[Hc], sab[Hc], smb[Hc], wa2s[Hc];
    __shared__ float att[Lc], wsoft[Lc], red[8];

    int bi = blockIdx.x;
    int b = bi >> 7, i = bi & 127;
    int tid = threadIdx.x;
    int j = tid & 127, kg = tid >> 7;

    // async copy both folded W matrices
    const float* gwa = g_Wca + l*Hc*Hc;
    const float* gwm = g_Wcm + l*Hc*Hc;
    #pragma unroll
    for(int q = 0; q < 8; q++){
        cp16(Wa + q*2048 + tid*4, gwa + q*2048 + tid*4);
        cp16(Wm + q*2048 + tid*4, gwm + q*2048 + tid*4);
    }
    asm volatile("cp.async.commit_group;");

    if(tid < 128){
        #pragma unroll
        for(int q = 0; q < 4; q++) we1s[q*Hc + tid] = We1[l*4*Hc + q*Hc + tid];
        be1s[tid] = be1[l*Hc + tid];
        sab[tid]  = g_sa[(size_t)bi*Hc + tid] + g_ba[l*Hc + tid];
        smb[tid]  = g_sm[(size_t)bi*Hc + tid] + g_bm[l*Hc + tid];
        wa2s[tid] = wa2[l*Hc + tid];
    }

    // edge features for this thread's j (j = tid&127)
    const float* hb_ = hist + (size_t)b*Lc*Dc;
    float lat_i = hb_[i*Dc + 0], lon_i = hb_[i*Dc + 1], src_i = hb_[i*Dc + 6];
    float ts_i = g_ts[b*Lc + i];
    float latj = hb_[j*Dc + 0], lonj = hb_[j*Dc + 1], srcj = hb_[j*Dc + 6];
    float tsj = g_ts[b*Lc + j];
    float dl = lat_i - latj, dn = lon_i - lonj;
    float dist = sqrtf(dl*dl + dn*dn + 1e-8f);
    float dtv = fabsf(ts_i - tsj) * (1.f/300.f);
    float ssv = (src_i == srcj) ? 1.f : 0.f;
    float diag = (j == i) ? 1.f : 0.f;
    float vldj = (mask[b*Lc + j] > 0.f) ? 1.f : 0.f;
    float vi   = (mask[b*Lc + i] > 0.f) ? 1.f : 0.f;
    __syncthreads();   // we1s/be1s ready

    // T build: thread owns column j, kg selects 32 k rows
    #pragma unroll 8
    for(int kk = 0; kk < 32; kk++){
        int k = kg*32 + kk;
        float v = dist*we1s[k] + dtv*we1s[Hc+k] + ssv*we1s[2*Hc+k] + diag*we1s[3*Hc+k] + be1s[k];
        Ts[k*Lc + j] = fmaxf(v, 0.f);
    }
    asm volatile("cp.async.wait_group 0;");
    __syncthreads();   // Ts + W ready

    // warp-specialized GEMM: group g (0=attention/Wa, 1=message/Wm)
    // thread: 8 j (jt..jt+7), 8 c ({ca..ca+3, cb..cb+3})
    int g  = tid >> 8;
    int t  = tid & 255;
    int tx = t & 15, ty = t >> 4;
    int jt = ty*8;
    int ca = tx*4, cb = 64 + tx*4;
    const float* Wg = g ? Wm : Wa;

    unsigned long long acc[32];
    #pragma unroll
    for(int q = 0; q < 32; q++) acc[q] = 0ull;

    #pragma unroll 2
    for(int k = 0; k < Hc; k++){
        const float* tr = &Ts[k*Lc + jt];
        float4 t0 = *(const float4*)tr;
        float4 t1 = *(const float4*)(tr + 4);
        const float* wr = &Wg[k*Hc];
        float4 w0 = *(const float4*)(wr + ca);
        float4 w1 = *(const float4*)(wr + cb);
        unsigned long long wp0 = pack2(w0.x,w0.y), wp1 = pack2(w0.z,w0.w);
        unsigned long long wp2 = pack2(w1.x,w1.y), wp3 = pack2(w1.z,w1.w);
        unsigned long long tp;
        tp = pack2(t0.x,t0.x); fma2(acc[0],tp,wp0);  fma2(acc[1],tp,wp1);  fma2(acc[2],tp,wp2);  fma2(acc[3],tp,wp3);
        tp = pack2(t0.y,t0.y); fma2(acc[4],tp,wp0);  fma2(acc[5],tp,wp1);  fma2(acc[6],tp,wp2);  fma2(acc[7],tp,wp3);
        tp = pack2(t0.z,t0.z); fma2(acc[8],tp,wp0);  fma2(acc[9],tp,wp1);  fma2(acc[10],tp,wp2); fma2(acc[11],tp,wp3);
        tp = pack2(t0.w,t0.w); fma2(acc[12],tp,wp0); fma2(acc[13],tp,wp1); fma2(acc[14],tp,wp2); fma2(acc[15],tp,wp3);
        tp = pack2(t1.x,t1.x); fma2(acc[16],tp,wp0); fma2(acc[17],tp,wp1); fma2(acc[18],tp,wp2); fma2(acc[19],tp,wp3);
        tp = pack2(t1.y,t1.y); fma2(acc[20],tp,wp0); fma2(acc[21],tp,wp1); fma2(acc[22],tp,wp2); fma2(acc[23],tp,wp3);
        tp = pack2(t1.z,t1.z); fma2(acc[24],tp,wp0); fma2(acc[25],tp,wp1); fma2(acc[26],tp,wp2); fma2(acc[27],tp,wp3);
        tp = pack2(t1.w,t1.w); fma2(acc[28],tp,wp0); fma2(acc[29],tp,wp1); fma2(acc[30],tp,wp2); fma2(acc[31],tp,wp3);
    }

    // ---------------- attention epilogue (group 0) ----------------
    if(g == 0){
        const float* dab = g_da + (size_t)b*Lc*Hc;
        #pragma unroll
        for(int jj = 0; jj < 8; jj++){
            int jr = jt + jj;
            float4 d0 = *(const float4*)&dab[(size_t)jr*Hc + ca];
            float4 d1 = *(const float4*)&dab[(size_t)jr*Hc + cb];
            float u0,u1,u2,u3,u4,u5,u6,u7;
            unpack2(acc[jj*4+0], u0, u1); unpack2(acc[jj*4+1], u2, u3);
            unpack2(acc[jj*4+2], u4, u5); unpack2(acc[jj*4+3], u6, u7);
            float s = 0.f;
            s += wa2s[ca+0]*tanh_fast(sab[ca+0] + d0.x + u0);
            s += wa2s[ca+1]*tanh_fast(sab[ca+1] + d0.y + u1);
            s += wa2s[ca+2]*tanh_fast(sab[ca+2] + d0.z + u2);
            s += wa2s[ca+3]*tanh_fast(sab[ca+3] + d0.w + u3);
            s += wa2s[cb+0]*tanh_fast(sab[cb+0] + d1.x + u4);
            s += wa2s[cb+1]*tanh_fast(sab[cb+1] + d1.y + u5);
            s += wa2s[cb+2]*tanh_fast(sab[cb+2] + d1.z + u6);
            s += wa2s[cb+3]*tanh_fast(sab[cb+3] + d1.w + u7);
            #pragma unroll
            for(int m = 8; m > 0; m >>= 1) s += __shfl_xor_sync(0xffffffffu, s, m);
            if(tx == 0) att[jr] = s;
        }
    }
    __syncthreads();

    // ---------------- softmax over j (first 128 threads) ----------------
    const float inv = 0.088388347648318440550f;   // 1/sqrt(128)
    float sc = -1e9f, e = 0.f;
    if(tid < 128){
        float a = (att[tid] + ba2[l]) * inv;
        bool ok = (vldj > 0.f) && (vi > 0.f);
        sc = ok ? a : -1e9f;
        float m = sc;
        #pragma unroll
        for(int s2 = 16; s2 > 0; s2 >>= 1) m = fmaxf(m, __shfl_xor_sync(0xffffffffu, m, s2));
        if((tid & 31) == 0) red[tid >> 5] = m;
    }
    __syncthreads();
    float bmax = fmaxf(fmaxf(red[0], red[1]), fmaxf(red[2], red[3]));
    if(tid < 128){
        e = expf(sc - bmax);
        float s2 = e;
        #pragma unroll
        for(int m = 16; m > 0; m >>= 1) s2 += __shfl_xor_sync(0xffffffffu, s2, m);
        if((tid & 31) == 0) red[4 + (tid >> 5)] = s2;
    }
    __syncthreads();
    if(tid < 128){
        float tot = red[4]+red[5]+red[6]+red[7];
        wsoft[tid] = e / tot;
    }
    __syncthreads();

    // ---------------- message epilogue (group 1): weighted relu aggregation ----------------
    float* su = dsm;   // 16 rows x 128 c partials (Ts region is dead now)
    if(g == 1){
        float agA[4], agB[4];
        #pragma unroll
        for(int p = 0; p < 4; p++){ agA[p] = 0.f; agB[p] = 0.f; }
        #pragma unroll
        for(int jj = 0; jj < 8; jj++){
            float wj = wsoft[jt + jj];
            float u0,u1,u2,u3,u4,u5,u6,u7;
            unpack2(acc[jj*4+0], u0, u1); unpack2(acc[jj*4+1], u2, u3);
            unpack2(acc[jj*4+2], u4, u5); unpack2(acc[jj*4+3], u6, u7);
            agA[0] += wj * fmaxf(smb[ca+0] + u0, 0.f);
            agA[1] += wj * fmaxf(smb[ca+1] + u1, 0.f);
            agA[2] += wj * fmaxf(smb[ca+2] + u2, 0.f);
            agA[3] += wj * fmaxf(smb[ca+3] + u3, 0.f);
            agB[0] += wj * fmaxf(smb[cb+0] + u4, 0.f);
            agB[1] += wj * fmaxf(smb[cb+1] + u5, 0.f);
            agB[2] += wj * fmaxf(smb[cb+2] + u6, 0.f);
            agB[3] += wj * fmaxf(smb[cb+3] + u7, 0.f);
        }
        #pragma unroll
        for(int p = 0; p < 4; p++){
            su[ty*Hc + ca + p] = agA[p];
            su[ty*Hc + cb + p] = agB[p];
        }
    }
    __syncthreads();
    if(tid < 128){
        float s = 0.f;
        #pragma unroll 4
        for(int t2 = 0; t2 < 16; t2++) s += su[t2*Hc + tid];
        g_aggpre[(size_t)bi*Hc + tid] = s;
    }
}

// ---------------- epilogue per 16 rows ----------------
__global__ __launch_bounds__(256)
void k_post2(int l, int has_next, const float* __restrict__ mask,
             const float* __restrict__ Wm2, const float* __restrict__ bm2,
             const float* __restrict__ Wo1, const float* __restrict__ bo1,
             const float* __restrict__ Wo2, const float* __restrict__ bo2,
             const float* __restrict__ lng, const float* __restrict__ lnb,
             const float* __restrict__ Wa1, const float* __restrict__ Wm1){
    int row0 = blockIdx.x * 16;
    int tid = threadIdx.x;
    int c = tid & 127, ty = tid >> 7;
    __shared__ float hs[16*Hc], as_[16*Hc], ag[16*Hc], op1[16*Hc];
    __shared__ float mu[16], rsd[16], vmsh[16];

    #pragma unroll
    for(int q = 0; q < 8; q++){
        int idx = q*256 + tid;
        hs[idx]  = g_h[(size_t)row0*Hc + idx];
        as_[idx] = g_aggpre[(size_t)row0*Hc + idx];
    }
    if(tid < 16) vmsh[tid] = mask[row0 + tid] > 0.f ? 1.f : 0.f;
    __syncthreads();

    float acc[8];
    const float* wm2 = Wm2 + l*Hc*Hc;
    #pragma unroll
    for(int p = 0; p < 8; p++) acc[p] = bm2[l*Hc + c];
    #pragma unroll 4
    for(int k = 0; k < Hc; k++){
        float w = wm2[k*Hc + c];
        #pragma unroll
        for(int p = 0; p < 8; p++) acc[p] += as_[(ty*8+p)*Hc + k] * w;
    }
    #pragma unroll
    for(int p = 0; p < 8; p++) ag[(ty*8+p)*Hc + c] = acc[p];
    __syncthreads();

    const float* wo1h = Wo1 + l*2*Hc*Hc;
    const float* wo1a = wo1h + Hc*Hc;
    #pragma unroll
    for(int p = 0; p < 8; p++) acc[p] = bo1[l*Hc + c];
    #pragma unroll 4
    for(int k = 0; k < Hc; k++){
        float w1 = wo1h[k*Hc + c], w2 = wo1a[k*Hc + c];
        #pragma unroll
        for(int p = 0; p < 8; p++)
            acc[p] += hs[(ty*8+p)*Hc + k]*w1 + ag[(ty*8+p)*Hc + k]*w2;
    }
    #pragma unroll
    for(int p = 0; p < 8; p++) op1[(ty*8+p)*Hc + c] = fmaxf(acc[p], 0.f);
    __syncthreads();

    const float* wo2 = Wo2 + l*Hc*Hc;
    #pragma unroll
    for(int p = 0; p < 8; p++) acc[p] = bo2[l*Hc + c];
    #pragma unroll 4
    for(int k = 0; k < Hc; k++){
        float w = wo2[k*Hc + c];
        #pragma unroll
        for(int p = 0; p < 8; p++) acc[p] += op1[(ty*8+p)*Hc + k] * w;
    }
    #pragma unroll
    for(int p = 0; p < 8; p++){
        int r = ty*8 + p;
        ag[r*Hc + c] = hs[r*Hc + c] + acc[p];
    }
    __syncthreads();

    {
        int row = tid >> 4, l16 = tid & 15;
        float s = 0.f, s2 = 0.f;
        #pragma unroll
        for(int q = 0; q < 8; q++){
            float v = ag[row*Hc + l16 + q*16];
            s += v; s2 += v*v;
        }
        #pragma unroll
        for(int m = 8; m > 0; m >>= 1){
            s  += __shfl_xor_sync(0xffffffffu, s, m);
            s2 += __shfl_xor_sync(0xffffffffu, s2, m);
        }
        if(l16 == 0){
            float m_ = s * (1.f/128.f);
            mu[row] = m_;
            rsd[row] = rsqrtf(s2 * (1.f/128.f) - m_*m_ + 1e-5f);
        }
    }
    __syncthreads();
    const float* lg = lng + l*Hc;
    const float* lb = lnb + l*Hc;
    #pragma unroll
    for(int p = 0; p < 8; p++){
        int r = ty*8 + p;
        float x = ag[r*Hc + c];
        float hn = ((x - mu[r]) * rsd[r] * lg[c] + lb[c]) * vmsh[r];
        g_h[(size_t)(row0+r)*Hc + c] = hn;
        hs[r*Hc + c] = hn;
    }

    if(has_next){
        __syncthreads();
        int ln = l + 1;
        const float* was = Wa1 + ln*3*Hc*Hc;
        const float* wad = was + Hc*Hc;
        const float* wms = Wm1 + ln*2*Hc*Hc;
        float aa[8], dd[8], mm[8];
        #pragma unroll
        for(int p = 0; p < 8; p++){ aa[p]=0.f; dd[p]=0.f; mm[p]=0.f; }
        #pragma unroll 4
        for(int k = 0; k < Hc; k++){
            float w1 = was[k*Hc + c], w2 = wad[k*Hc + c], w3 = wms[k*Hc + c];
            #pragma unroll
            for(int p = 0; p < 8; p++){
                float h = hs[(ty*8+p)*Hc + k];
                aa[p] += h*w1; dd[p] += h*w2; mm[p] += h*w3;
            }
        }
        #pragma unroll
        for(int p = 0; p < 8; p++){
            size_t r = (size_t)(row0 + ty*8 + p)*Hc + c;
            g_sa[r] = aa[p]; g_da[r] = dd[p]; g_sm[r] = mm[p];
        }
    }
}

// ---------------- decoder ----------------
__global__ void k_dec(const float* __restrict__ hist, const float* __restrict__ mask,
                      const float* __restrict__ hg, const float* __restrict__ hb,
                      const float* __restrict__ Wh1, const float* __restrict__ bh1,
                      const float* __restrict__ Wh2, const float* __restrict__ bh2,
                      float* __restrict__ out){
    int b = blockIdx.x; int t = threadIdx.x;
    __shared__ float x[136], xn[136], hid[Hc];
    __shared__ float red2[4];
    float mv = mask[b*Lc + t];
    float s = mv;
    #pragma unroll
    for(int sft = 16; sft > 0; sft >>= 1) s += __shfl_xor_sync(0xffffffffu, s, sft);
    if((t & 31) == 0) red2[t >> 5] = s;
    __syncthreads();
    float tot = red2[0]+red2[1]+red2[2]+red2[3];
    int vc = (int)tot;
    vc = min(max(vc, 1), Lc);
    int last = vc - 1;

    if(t < Dc) x[t] = hist[((size_t)b*Lc + last)*Dc + t];
    x[Dc + t] = g_h[((size_t)b*Lc + last)*Hc + t];
    __syncthreads();
    float s1 = x[t] + ((t < 8) ? x[128 + t] : 0.f);
    #pragma unroll
    for(int sft = 16; sft > 0; sft >>= 1) s1 += __shfl_xor_sync(0xffffffffu, s1, sft);
    __syncthreads();
    if((t & 31) == 0) red2[t >> 5] = s1;
    __syncthreads();
    float mu = (red2[0]+red2[1]+red2[2]+red2[3]) * (1.f/136.f);
    float d0 = x[t] - mu;
    float s2 = d0*d0;
    if(t < 8){ float d1 = x[128 + t] - mu; s2 += d1*d1; }
    #pragma unroll
    for(int sft = 16; sft > 0; sft >>= 1) s2 += __shfl_xor_sync(0xffffffffu, s2, sft);
    __syncthreads();
    if((t & 31) == 0) red2[t >> 5] = s2;
    __syncthreads();
    float rs = rsqrtf((red2[0]+red2[1]+red2[2]+red2[3]) * (1.f/136.f) + 1e-5f);
    xn[t] = (x[t] - mu) * rs * hg[t] + hb[t];
    if(t < 8) xn[128 + t] = (x[128 + t] - mu) * rs * hg[128 + t] + hb[128 + t];
    __syncthreads();
    float h_ = bh1[t];
    for(int k = 0; k < 136; k++) h_ += xn[k]*Wh1[k*Hc + t];
    hid[t] = fmaxf(h_, 0.f);
    __syncthreads();
    if(t < 24){
        float p = bh2[t];
        for(int k = 0; k < Hc; k++) p += hid[k]*Wh2[k*24 + t];
        if(isnan(p)) p = 0.f;
        else if(isinf(p)) p = (p > 0.f) ? 1e4f : -1e4f;
        out[b*24 + t] = p;
    }
}

__global__ void k_copyh(float* __restrict__ out){
    int i = blockIdx.x*blockDim.x + threadIdx.x;
    out[384 + i] = g_h[i];
}

// ---------------- launch ----------------
extern "C" void kernel_launch(void* const* d_in, const int* in_sizes, int n_in,
                              void* d_out, int out_size){
    const float* hist = (const float*)d_in[0];
    const float* mask = (const float*)d_in[1];
    const float* Wp   = (const float*)d_in[2];
    const float* bp   = (const float*)d_in[3];
    const float* We1  = (const float*)d_in[4];
    const float* be1  = (const float*)d_in[5];
    const float* We2  = (const float*)d_in[6];
    const float* be2  = (const float*)d_in[7];
    const float* Wa1  = (const float*)d_in[8];
    const float* ba1  = (const float*)d_in[9];
    const float* wa2  = (const float*)d_in[10];
    const float* ba2  = (const float*)d_in[11];
    const float* Wm1  = (const float*)d_in[12];
    const float* bm1  = (const float*)d_in[13];
    const float* Wm2  = (const float*)d_in[14];
    const float* bm2  = (const float*)d_in[15];
    const float* Wo1  = (const float*)d_in[16];
    const float* bo1  = (const float*)d_in[17];
    const float* Wo2  = (const float*)d_in[18];
    const float* bo2  = (const float*)d_in[19];
    const float* lng  = (const float*)d_in[20];
    const float* lnb  = (const float*)d_in[21];
    const float* hg   = (const float*)d_in[22];
    const float* hbv  = (const float*)d_in[23];
    const float* Wh1  = (const float*)d_in[24];
    const float* bh1  = (const float*)d_in[25];
    const float* Wh2  = (const float*)d_in[26];
    const float* bh2  = (const float*)d_in[27];
    float* out = (float*)d_out;

    cudaFuncSetAttribute(k_main3, cudaFuncAttributeMaxDynamicSharedMemorySize, 196608);

    k_ts<<<1, 32>>>(hist);
    k_prepwb<<<NLc*129, Hc>>>(We2, be2, Wa1, Wm1, ba1, bm1);
    k_h0s<<<Bc*Lc/16, 256>>>(hist, mask, Wp, bp, Wa1, Wm1);
    for(int l = 0; l < NLc; l++){
        k_main3<<<Bc*Lc, 512, 196608>>>(l, hist, mask, We1, be1, wa2, ba2);
        k_post2<<<Bc*Lc/16, 256>>>(l, (l+1 < NLc) ? 1 : 0, mask,
                                   Wm2, bm2, Wo1, bo1, Wo2, bo2, lng, lnb, Wa1, Wm1);
    }
    k_dec<<<Bc, Hc>>>(hist, mask, hg, hbv, Wh1, bh1, Wh2, bh2, out);
    if(out_size >= 384 + Bc*Lc*Hc){
        k_copyh<<<(Bc*Lc*Hc)/256, 256>>>(out);
    }
}